// round 1
// baseline (speedup 1.0000x reference)
#include <cuda_runtime.h>
#include <math.h>

#define NB 2
#define SS 2048
#define NH 16
#define HD 64
#define DD 1024
#define D3 3072
#define MTOT (NB*SS)
#define FPAD 68

// Scratch (allocation-free rule: device globals)
__device__ float g_q[NB*NH*SS*HD];     // [B,H,S,hd]
__device__ float g_k[NB*NH*SS*HD];
__device__ float g_v[NB*NH*SS*HD];
__device__ float g_attn[MTOT*DD];      // merged heads [B*S, D]

// ---------------------------------------------------------------------------
// QKV GEMM: qkv = hs[4096,1024] @ w_attn[1024,3072] + b_attn + lora
// scattered into g_q/g_k/g_v with head split.
// 128x128 block tile, BK=8, 256 threads, 8x8 register tile per thread.
// ---------------------------------------------------------------------------
__global__ __launch_bounds__(256)
void qkv_gemm(const float* __restrict__ A, const float* __restrict__ W,
              const float* __restrict__ bias, const float* __restrict__ lora)
{
    __shared__ float As[8][128];   // [k][m] (transposed)
    __shared__ float Bs[8][128];   // [k][n]
    const int K = DD, N = D3;
    const int tid = threadIdx.x;
    const int bm = blockIdx.y * 128, bn = blockIdx.x * 128;
    const int ty = tid >> 4, tx = tid & 15;
    const int arow = tid >> 1, acol = (tid & 1) * 4;
    const int brow = tid >> 5, bcol = (tid & 31) * 4;

    float acc[8][8];
#pragma unroll
    for (int i = 0; i < 8; i++)
#pragma unroll
        for (int j = 0; j < 8; j++) acc[i][j] = 0.f;

    for (int k0 = 0; k0 < K; k0 += 8) {
        float4 a4 = *(const float4*)(A + (size_t)(bm + arow) * K + k0 + acol);
        As[acol + 0][arow] = a4.x;
        As[acol + 1][arow] = a4.y;
        As[acol + 2][arow] = a4.z;
        As[acol + 3][arow] = a4.w;
        *(float4*)&Bs[brow][bcol] =
            *(const float4*)(W + (size_t)(k0 + brow) * N + bn + bcol);
        __syncthreads();
#pragma unroll
        for (int kk = 0; kk < 8; kk++) {
            float ra[8], rb[8];
            *(float4*)&ra[0] = *(float4*)&As[kk][ty * 4];
            *(float4*)&ra[4] = *(float4*)&As[kk][64 + ty * 4];
            *(float4*)&rb[0] = *(float4*)&Bs[kk][tx * 4];
            *(float4*)&rb[4] = *(float4*)&Bs[kk][64 + tx * 4];
#pragma unroll
            for (int i = 0; i < 8; i++)
#pragma unroll
                for (int j = 0; j < 8; j++)
                    acc[i][j] += ra[i] * rb[j];
        }
        __syncthreads();
    }

    // epilogue: + bias + lora, scatter into q/k/v [B,H,S,hd], float4 stores
    const int b = (bm >> 11);  // bm + row stays within same b? no: compute per-row below
#pragma unroll
    for (int i = 0; i < 8; i++) {
        int row = bm + ((i < 4) ? (ty * 4 + i) : (64 + ty * 4 + (i - 4)));
        int bb_ = row >> 11;           // batch
        int s   = row & 2047;          // seq pos
#pragma unroll
        for (int jg = 0; jg < 2; jg++) {
            int col = bn + jg * 64 + tx * 4;
            float4 bi = *(const float4*)(bias + col);
            float4 lo = *(const float4*)(lora + (size_t)row * D3 + col);
            float4 v;
            v.x = acc[i][jg * 4 + 0] + bi.x + lo.x;
            v.y = acc[i][jg * 4 + 1] + bi.y + lo.y;
            v.z = acc[i][jg * 4 + 2] + bi.z + lo.z;
            v.w = acc[i][jg * 4 + 3] + bi.w + lo.w;
            int which = col >> 10;
            int rr = col & 1023;
            int h = rr >> 6, d = rr & 63;
            float* dst = (which == 0) ? g_q : (which == 1) ? g_k : g_v;
            *(float4*)(dst + ((size_t)((bb_ * NH + h) * SS + s)) * HD + d) = v;
        }
    }
    (void)b;
}

// ---------------------------------------------------------------------------
// Flash attention, fp32, causal. One block = one (b,h) x one 64-row Q tile.
// 256 threads as 16x16, 4x4 register tiles for both S=QK^T and O=PV GEMMs.
// Dynamic smem: Qs/Ks[d][r|c], Vs[c][d], Ps[c][r], each [64][68].
// ---------------------------------------------------------------------------
__global__ __launch_bounds__(256)
void flash_attn()
{
    extern __shared__ float sm[];
    float* Qs = sm;                   // [d][r]
    float* Ks = Qs + 64 * FPAD;       // [d][c]
    float* Vs = Ks + 64 * FPAD;       // [c][d]
    float* Ps = Vs + 64 * FPAD;       // [c][r]

    const int qi = blockIdx.x;        // q tile index 0..31
    const int bh = blockIdx.y;        // 0..31
    const float* Qg = g_q + (size_t)bh * SS * HD;
    const float* Kg = g_k + (size_t)bh * SS * HD;
    const float* Vg = g_v + (size_t)bh * SS * HD;

    const int tid = threadIdx.x;
    const int ty = tid >> 4, tx = tid & 15;

    // load Q tile transposed
#pragma unroll
    for (int it = 0; it < 4; it++) {
        int idx = tid + it * 256;          // one float4 each
        int r = idx >> 4; int d4 = (idx & 15) * 4;
        float4 t = *(const float4*)(Qg + (size_t)(qi * 64 + r) * HD + d4);
        Qs[(d4 + 0) * FPAD + r] = t.x;
        Qs[(d4 + 1) * FPAD + r] = t.y;
        Qs[(d4 + 2) * FPAD + r] = t.z;
        Qs[(d4 + 3) * FPAD + r] = t.w;
    }

    float o[4][4];
    float mrow[4], lrow[4];
#pragma unroll
    for (int i = 0; i < 4; i++) {
        mrow[i] = -1e30f; lrow[i] = 0.f;
#pragma unroll
        for (int j = 0; j < 4; j++) o[i][j] = 0.f;
    }
    __syncthreads();

    for (int j = 0; j <= qi; j++) {
        // load K (transposed) and V (natural) tiles
#pragma unroll
        for (int it = 0; it < 4; it++) {
            int idx = tid + it * 256;
            int c = idx >> 4; int d4 = (idx & 15) * 4;
            float4 t = *(const float4*)(Kg + (size_t)(j * 64 + c) * HD + d4);
            Ks[(d4 + 0) * FPAD + c] = t.x;
            Ks[(d4 + 1) * FPAD + c] = t.y;
            Ks[(d4 + 2) * FPAD + c] = t.z;
            Ks[(d4 + 3) * FPAD + c] = t.w;
            float4 u = *(const float4*)(Vg + (size_t)(j * 64 + c) * HD + d4);
            *(float4*)(Vs + c * FPAD + d4) = u;
        }
        __syncthreads();

        // S = Q K^T (64x64x64), 4x4 per thread
        float s[4][4];
#pragma unroll
        for (int ii = 0; ii < 4; ii++)
#pragma unroll
            for (int jj = 0; jj < 4; jj++) s[ii][jj] = 0.f;

#pragma unroll 8
        for (int d = 0; d < 64; d++) {
            float4 qa = *(float4*)(Qs + d * FPAD + ty * 4);
            float4 kb = *(float4*)(Ks + d * FPAD + tx * 4);
            float aq[4] = {qa.x, qa.y, qa.z, qa.w};
            float bk[4] = {kb.x, kb.y, kb.z, kb.w};
#pragma unroll
            for (int ii = 0; ii < 4; ii++)
#pragma unroll
                for (int jj = 0; jj < 4; jj++)
                    s[ii][jj] += aq[ii] * bk[jj];
        }
#pragma unroll
        for (int ii = 0; ii < 4; ii++)
#pragma unroll
            for (int jj = 0; jj < 4; jj++) s[ii][jj] *= 0.125f;

        // causal mask on the diagonal tile
        if (j == qi) {
#pragma unroll
            for (int ii = 0; ii < 4; ii++)
#pragma unroll
                for (int jj = 0; jj < 4; jj++)
                    if (tx * 4 + jj > ty * 4 + ii) s[ii][jj] = -1e30f;
        }

        // online softmax per row (16 tx-lanes share each row; butterfly allreduce)
#pragma unroll
        for (int ii = 0; ii < 4; ii++) {
            float mx = fmaxf(fmaxf(s[ii][0], s[ii][1]), fmaxf(s[ii][2], s[ii][3]));
            mx = fmaxf(mx, __shfl_xor_sync(0xffffffffu, mx, 1));
            mx = fmaxf(mx, __shfl_xor_sync(0xffffffffu, mx, 2));
            mx = fmaxf(mx, __shfl_xor_sync(0xffffffffu, mx, 4));
            mx = fmaxf(mx, __shfl_xor_sync(0xffffffffu, mx, 8));
            float newm = fmaxf(mrow[ii], mx);
            float corr = __expf(mrow[ii] - newm);
            float rsum = 0.f;
#pragma unroll
            for (int jj = 0; jj < 4; jj++) {
                s[ii][jj] = __expf(s[ii][jj] - newm);
                rsum += s[ii][jj];
            }
            rsum += __shfl_xor_sync(0xffffffffu, rsum, 1);
            rsum += __shfl_xor_sync(0xffffffffu, rsum, 2);
            rsum += __shfl_xor_sync(0xffffffffu, rsum, 4);
            rsum += __shfl_xor_sync(0xffffffffu, rsum, 8);
            lrow[ii] = lrow[ii] * corr + rsum;
            mrow[ii] = newm;
#pragma unroll
            for (int jj = 0; jj < 4; jj++) o[ii][jj] *= corr;
        }

        // stage P transposed for the PV GEMM
#pragma unroll
        for (int ii = 0; ii < 4; ii++)
#pragma unroll
            for (int jj = 0; jj < 4; jj++)
                Ps[(tx * 4 + jj) * FPAD + ty * 4 + ii] = s[ii][jj];
        __syncthreads();

        // O += P V (64x64x64)
#pragma unroll 8
        for (int c = 0; c < 64; c++) {
            float4 pa = *(float4*)(Ps + c * FPAD + ty * 4);
            float4 vb = *(float4*)(Vs + c * FPAD + tx * 4);
            float ap[4] = {pa.x, pa.y, pa.z, pa.w};
            float bv[4] = {vb.x, vb.y, vb.z, vb.w};
#pragma unroll
            for (int ii = 0; ii < 4; ii++)
#pragma unroll
                for (int jj = 0; jj < 4; jj++)
                    o[ii][jj] += ap[ii] * bv[jj];
        }
        __syncthreads();
    }

    // normalize + store merged heads [B*S, D]
    const int b = bh >> 4, h = bh & 15;
#pragma unroll
    for (int ii = 0; ii < 4; ii++) {
        int r = qi * 64 + ty * 4 + ii;
        float inv = 1.f / lrow[ii];
        float4 v;
        v.x = o[ii][0] * inv; v.y = o[ii][1] * inv;
        v.z = o[ii][2] * inv; v.w = o[ii][3] * inv;
        *(float4*)(g_attn + (size_t)(b * SS + r) * DD + h * HD + tx * 4) = v;
    }
}

// ---------------------------------------------------------------------------
// Output projection: out = g_attn[4096,1024] @ w_proj[1024,1024] + b_proj
// ---------------------------------------------------------------------------
__global__ __launch_bounds__(256)
void proj_gemm(const float* __restrict__ W, const float* __restrict__ bias,
               float* __restrict__ C)
{
    __shared__ float As[8][128];
    __shared__ float Bs[8][128];
    const float* A = g_attn;
    const int K = DD, N = DD;
    const int tid = threadIdx.x;
    const int bm = blockIdx.y * 128, bn = blockIdx.x * 128;
    const int ty = tid >> 4, tx = tid & 15;
    const int arow = tid >> 1, acol = (tid & 1) * 4;
    const int brow = tid >> 5, bcol = (tid & 31) * 4;

    float acc[8][8];
#pragma unroll
    for (int i = 0; i < 8; i++)
#pragma unroll
        for (int j = 0; j < 8; j++) acc[i][j] = 0.f;

    for (int k0 = 0; k0 < K; k0 += 8) {
        float4 a4 = *(const float4*)(A + (size_t)(bm + arow) * K + k0 + acol);
        As[acol + 0][arow] = a4.x;
        As[acol + 1][arow] = a4.y;
        As[acol + 2][arow] = a4.z;
        As[acol + 3][arow] = a4.w;
        *(float4*)&Bs[brow][bcol] =
            *(const float4*)(W + (size_t)(k0 + brow) * N + bn + bcol);
        __syncthreads();
#pragma unroll
        for (int kk = 0; kk < 8; kk++) {
            float ra[8], rb[8];
            *(float4*)&ra[0] = *(float4*)&As[kk][ty * 4];
            *(float4*)&ra[4] = *(float4*)&As[kk][64 + ty * 4];
            *(float4*)&rb[0] = *(float4*)&Bs[kk][tx * 4];
            *(float4*)&rb[4] = *(float4*)&Bs[kk][64 + tx * 4];
#pragma unroll
            for (int i = 0; i < 8; i++)
#pragma unroll
                for (int j = 0; j < 8; j++)
                    acc[i][j] += ra[i] * rb[j];
        }
        __syncthreads();
    }

#pragma unroll
    for (int i = 0; i < 8; i++) {
        int row = bm + ((i < 4) ? (ty * 4 + i) : (64 + ty * 4 + (i - 4)));
#pragma unroll
        for (int jg = 0; jg < 2; jg++) {
            int col = bn + jg * 64 + tx * 4;
            float4 bi = *(const float4*)(bias + col);
            float4 v;
            v.x = acc[i][jg * 4 + 0] + bi.x;
            v.y = acc[i][jg * 4 + 1] + bi.y;
            v.z = acc[i][jg * 4 + 2] + bi.z;
            v.w = acc[i][jg * 4 + 3] + bi.w;
            *(float4*)(C + (size_t)row * N + col) = v;
        }
    }
}

// ---------------------------------------------------------------------------
extern "C" void kernel_launch(void* const* d_in, const int* in_sizes, int n_in,
                              void* d_out, int out_size)
{
    const float* hs     = (const float*)d_in[0];
    const float* lora   = (const float*)d_in[1];
    const float* w_attn = (const float*)d_in[2];
    const float* b_attn = (const float*)d_in[3];
    const float* w_proj = (const float*)d_in[4];
    const float* b_proj = (const float*)d_in[5];
    float* out = (float*)d_out;

    // idempotent, no-stream, no-alloc: safe under graph capture
    cudaFuncSetAttribute(flash_attn, cudaFuncAttributeMaxDynamicSharedMemorySize,
                         4 * 64 * FPAD * (int)sizeof(float));

    qkv_gemm<<<dim3(D3 / 128, MTOT / 128), 256>>>(hs, w_attn, b_attn, lora);
    flash_attn<<<dim3(SS / 64, NB * NH), 256, 4 * 64 * FPAD * sizeof(float)>>>();
    proj_gemm<<<dim3(DD / 128, MTOT / 128), 256>>>(w_proj, b_proj, out);
}

// round 2
// speedup vs baseline: 3.4126x; 3.4126x over previous
#include <cuda_runtime.h>
#include <math.h>

#define NB 2
#define SS 2048
#define NH 16
#define HD 64
#define DD 1024
#define D3 3072
#define MTOT (NB*SS)

// Scratch (allocation-free rule: device globals)
__device__ float g_q[NB*NH*SS*HD];     // [B,H,S,hd]
__device__ float g_k[NB*NH*SS*HD];
__device__ float g_v[NB*NH*SS*HD];
__device__ float g_attn[MTOT*DD];      // merged heads [B*S, D]

__device__ __forceinline__ unsigned f2t(float x) {
    unsigned u;
    asm("cvt.rna.tf32.f32 %0, %1;" : "=r"(u) : "f"(x));
    return u;
}

__device__ __forceinline__ void mma8(float* d, const unsigned* a, const unsigned* b) {
    asm volatile(
        "mma.sync.aligned.m16n8k8.row.col.f32.tf32.tf32.f32 "
        "{%0,%1,%2,%3}, {%4,%5,%6,%7}, {%8,%9}, {%0,%1,%2,%3};\n"
        : "+f"(d[0]), "+f"(d[1]), "+f"(d[2]), "+f"(d[3])
        : "r"(a[0]), "r"(a[1]), "r"(a[2]), "r"(a[3]), "r"(b[0]), "r"(b[1]));
}

// ---------------------------------------------------------------------------
// TF32 GEMM: C[M,N] = A[M,1024] @ W[1024,N] (+bias) (+lora, scatter q/k/v)
// 128x128 block tile, BK=32, 256 threads (8 warps as 4x2), warp tile 32x64.
// Double-buffered smem. As[m][k] stride 36, Bs[k][n] stride 136.
// ---------------------------------------------------------------------------
#define ASTR 36
#define BSTR 136
#define ABUF (128*ASTR)          // 4608 u32
#define BBUF (32*BSTR)           // 4352 u32
#define GBUF (ABUF + BBUF)       // per stage
#define GSMEM (2*GBUF*4)         // bytes = 71680

template<int N, bool QKV>
__global__ __launch_bounds__(256)
void gemm_tf32(const float* __restrict__ Ain, const float* __restrict__ W,
               const float* __restrict__ bias, const float* __restrict__ lora,
               float* __restrict__ C)
{
    extern __shared__ unsigned sg[];
    const float* A = QKV ? Ain : g_attn;
    const int K = DD;

    const int tid  = threadIdx.x;
    const int warp = tid >> 5, lane = tid & 31;
    const int g = lane >> 2, t = lane & 3;
    const int wm = warp & 3, wn = warp >> 2;         // 4 x 2 warps
    const int bm = blockIdx.y * 128, bn = blockIdx.x * 128;

    // global load coords
    const int rowA = tid >> 3, kqA = tid & 7;        // A: 4 rows strided 32
    const int kB = tid >> 3, cqB = tid & 7;          // B: row kB, 4 col-quads

    float acc[2][8][4];
#pragma unroll
    for (int mf = 0; mf < 2; mf++)
#pragma unroll
        for (int nf = 0; nf < 8; nf++)
#pragma unroll
            for (int e = 0; e < 4; e++) acc[mf][nf][e] = 0.f;

    float4 ra[4], rb[4];

    // prologue: tile 0
#pragma unroll
    for (int i = 0; i < 4; i++)
        ra[i] = *(const float4*)(A + (size_t)(bm + rowA + 32 * i) * K + kqA * 4);
#pragma unroll
    for (int i = 0; i < 4; i++)
        rb[i] = *(const float4*)(W + (size_t)kB * N + bn + (cqB + 8 * i) * 4);

    unsigned* As = sg;
    unsigned* Bs = sg + ABUF;
#pragma unroll
    for (int i = 0; i < 4; i++) {
        uint4 u = make_uint4(f2t(ra[i].x), f2t(ra[i].y), f2t(ra[i].z), f2t(ra[i].w));
        *(uint4*)(As + (rowA + 32 * i) * ASTR + kqA * 4) = u;
        uint4 v = make_uint4(f2t(rb[i].x), f2t(rb[i].y), f2t(rb[i].z), f2t(rb[i].w));
        *(uint4*)(Bs + kB * BSTR + (cqB + 8 * i) * 4) = v;
    }
    __syncthreads();

    const int NT = K / 32;   // 32 iterations
    for (int it = 0; it < NT; ++it) {
        if (it < NT - 1) {
            int k0 = (it + 1) * 32;
#pragma unroll
            for (int i = 0; i < 4; i++)
                ra[i] = *(const float4*)(A + (size_t)(bm + rowA + 32 * i) * K + k0 + kqA * 4);
#pragma unroll
            for (int i = 0; i < 4; i++)
                rb[i] = *(const float4*)(W + (size_t)(k0 + kB) * N + bn + (cqB + 8 * i) * 4);
        }

        const unsigned* Ac = sg + (it & 1) * GBUF;
        const unsigned* Bc = Ac + ABUF;
#pragma unroll
        for (int ks = 0; ks < 4; ks++) {
            const int kb = ks * 8;
            unsigned ua[2][4];
#pragma unroll
            for (int mf = 0; mf < 2; mf++) {
                int rbm = wm * 32 + mf * 16;
                ua[mf][0] = Ac[(rbm + g) * ASTR + kb + t];
                ua[mf][1] = Ac[(rbm + g + 8) * ASTR + kb + t];
                ua[mf][2] = Ac[(rbm + g) * ASTR + kb + t + 4];
                ua[mf][3] = Ac[(rbm + g + 8) * ASTR + kb + t + 4];
            }
#pragma unroll
            for (int nf = 0; nf < 8; nf++) {
                unsigned ub[2];
                int col = wn * 64 + nf * 8 + g;
                ub[0] = Bc[(kb + t) * BSTR + col];
                ub[1] = Bc[(kb + t + 4) * BSTR + col];
                mma8(acc[0][nf], ua[0], ub);
                mma8(acc[1][nf], ua[1], ub);
            }
        }

        if (it < NT - 1) {
            unsigned* An = sg + ((it + 1) & 1) * GBUF;
            unsigned* Bn = An + ABUF;
#pragma unroll
            for (int i = 0; i < 4; i++) {
                uint4 u = make_uint4(f2t(ra[i].x), f2t(ra[i].y), f2t(ra[i].z), f2t(ra[i].w));
                *(uint4*)(An + (rowA + 32 * i) * ASTR + kqA * 4) = u;
                uint4 v = make_uint4(f2t(rb[i].x), f2t(rb[i].y), f2t(rb[i].z), f2t(rb[i].w));
                *(uint4*)(Bn + kB * BSTR + (cqB + 8 * i) * 4) = v;
            }
            __syncthreads();
        }
    }

    // epilogue
#pragma unroll
    for (int mf = 0; mf < 2; mf++) {
#pragma unroll
        for (int nf = 0; nf < 8; nf++) {
            int c = bn + wn * 64 + nf * 8 + 2 * t;
            float2 bi = *(const float2*)(bias + c);
#pragma unroll
            for (int half = 0; half < 2; half++) {
                int r = bm + wm * 32 + mf * 16 + g + half * 8;
                float v0 = acc[mf][nf][half * 2 + 0] + bi.x;
                float v1 = acc[mf][nf][half * 2 + 1] + bi.y;
                if (QKV) {
                    float2 lo = *(const float2*)(lora + (size_t)r * D3 + c);
                    v0 += lo.x; v1 += lo.y;
                    int which = c >> 10, rr = c & 1023;
                    int h = rr >> 6, d = rr & 63;
                    int b_ = r >> 11, s = r & 2047;
                    float* dst = (which == 0) ? g_q : (which == 1) ? g_k : g_v;
                    *(float2*)(dst + ((size_t)((b_ * NH + h) * SS + s)) * HD + d) =
                        make_float2(v0, v1);
                } else {
                    *(float2*)(C + (size_t)r * N + c) = make_float2(v0, v1);
                }
            }
        }
    }
}

// ---------------------------------------------------------------------------
// Flash attention, tf32 mma, causal. Block = (bh, 64-row q tile), 4 warps.
// Warp w owns rows w*16..w*16+15 (all 64 key cols / all 64 d cols).
// Smem: Ks[64][68], Vs[64][72], Ps[64][68] (Ps doubles as Q staging).
// ---------------------------------------------------------------------------
#define KSTR 68
#define VSTR 72
#define PSTR 68
#define FSMEM ((64*KSTR + 64*VSTR + 64*PSTR) * 4)   // 53248 bytes

__global__ __launch_bounds__(128)
void flash_tf32()
{
    extern __shared__ unsigned smf[];
    unsigned* Ks = smf;
    unsigned* Vs = Ks + 64 * KSTR;
    unsigned* Ps = Vs + 64 * VSTR;

    const int qi = (int)gridDim.x - 1 - (int)blockIdx.x;   // heavy blocks first
    const int bh = blockIdx.y;
    const float* Qg = g_q + (size_t)bh * SS * HD;
    const float* Kg = g_k + (size_t)bh * SS * HD;
    const float* Vg = g_v + (size_t)bh * SS * HD;

    const int tid = threadIdx.x;
    const int warp = tid >> 5, lane = tid & 31;
    const int g = lane >> 2, t = lane & 3;
    const int rb = warp * 16;

    // stage Q (raw bits) into Ps area
#pragma unroll
    for (int i = 0; i < 8; i++) {
        int idx = tid + i * 128;
        int r = idx >> 4, d4 = (idx & 15) * 4;
        float4 q4 = *(const float4*)(Qg + (size_t)(qi * 64 + r) * HD + d4);
        *(uint4*)(Ps + r * PSTR + d4) =
            make_uint4(__float_as_uint(q4.x), __float_as_uint(q4.y),
                       __float_as_uint(q4.z), __float_as_uint(q4.w));
    }
    __syncthreads();

    // build Q fragments (scaled by 1/8, tf32)
    unsigned qa[8][4];
#pragma unroll
    for (int j8 = 0; j8 < 8; j8++) {
        qa[j8][0] = f2t(__uint_as_float(Ps[(rb + g) * PSTR + j8 * 8 + t]) * 0.125f);
        qa[j8][1] = f2t(__uint_as_float(Ps[(rb + g + 8) * PSTR + j8 * 8 + t]) * 0.125f);
        qa[j8][2] = f2t(__uint_as_float(Ps[(rb + g) * PSTR + j8 * 8 + t + 4]) * 0.125f);
        qa[j8][3] = f2t(__uint_as_float(Ps[(rb + g + 8) * PSTR + j8 * 8 + t + 4]) * 0.125f);
    }

    float o[8][4];
#pragma unroll
    for (int nf = 0; nf < 8; nf++)
#pragma unroll
        for (int e = 0; e < 4; e++) o[nf][e] = 0.f;
    float ml = -1e30f, mh = -1e30f, ll = 0.f, lh = 0.f;

    for (int j = 0; j <= qi; j++) {
        __syncthreads();   // prior iter done with Ks/Vs (and Q staging on iter 0)
        // load K,V tile (tf32-converted)
#pragma unroll
        for (int i = 0; i < 8; i++) {
            int idx = tid + i * 128;
            int r = idx >> 4, d4 = (idx & 15) * 4;
            float4 k4 = *(const float4*)(Kg + (size_t)(j * 64 + r) * HD + d4);
            *(uint4*)(Ks + r * KSTR + d4) =
                make_uint4(f2t(k4.x), f2t(k4.y), f2t(k4.z), f2t(k4.w));
            float4 v4 = *(const float4*)(Vg + (size_t)(j * 64 + r) * HD + d4);
            *(uint4*)(Vs + r * VSTR + d4) =
                make_uint4(f2t(v4.x), f2t(v4.y), f2t(v4.z), f2t(v4.w));
        }
        __syncthreads();

        // S = Q K^T  (rows rb..rb+15 x 64 keys)
        float s[8][4];
#pragma unroll
        for (int nf = 0; nf < 8; nf++) {
#pragma unroll
            for (int e = 0; e < 4; e++) s[nf][e] = 0.f;
#pragma unroll
            for (int j8 = 0; j8 < 8; j8++) {
                unsigned kb[2];
                kb[0] = Ks[(nf * 8 + g) * KSTR + j8 * 8 + t];
                kb[1] = Ks[(nf * 8 + g) * KSTR + j8 * 8 + t + 4];
                mma8(s[nf], qa[j8], kb);
            }
        }

        // causal mask on diagonal tile
        if (j == qi) {
#pragma unroll
            for (int nf = 0; nf < 8; nf++) {
                int c0 = nf * 8 + 2 * t, c1 = c0 + 1;
                int rlo = rb + g, rhi = rlo + 8;
                if (c0 > rlo) s[nf][0] = -1e30f;
                if (c1 > rlo) s[nf][1] = -1e30f;
                if (c0 > rhi) s[nf][2] = -1e30f;
                if (c1 > rhi) s[nf][3] = -1e30f;
            }
        }

        // online softmax (rows rlo = rb+g, rhi = rb+g+8)
        float mxl = -1e30f, mxh = -1e30f;
#pragma unroll
        for (int nf = 0; nf < 8; nf++) {
            mxl = fmaxf(mxl, fmaxf(s[nf][0], s[nf][1]));
            mxh = fmaxf(mxh, fmaxf(s[nf][2], s[nf][3]));
        }
        mxl = fmaxf(mxl, __shfl_xor_sync(0xffffffffu, mxl, 1));
        mxl = fmaxf(mxl, __shfl_xor_sync(0xffffffffu, mxl, 2));
        mxh = fmaxf(mxh, __shfl_xor_sync(0xffffffffu, mxh, 1));
        mxh = fmaxf(mxh, __shfl_xor_sync(0xffffffffu, mxh, 2));
        float nml = fmaxf(ml, mxl), nmh = fmaxf(mh, mxh);
        float cl = __expf(ml - nml), ch = __expf(mh - nmh);
        float suml = 0.f, sumh = 0.f;
#pragma unroll
        for (int nf = 0; nf < 8; nf++) {
            s[nf][0] = __expf(s[nf][0] - nml);
            s[nf][1] = __expf(s[nf][1] - nml);
            s[nf][2] = __expf(s[nf][2] - nmh);
            s[nf][3] = __expf(s[nf][3] - nmh);
            suml += s[nf][0] + s[nf][1];
            sumh += s[nf][2] + s[nf][3];
        }
        suml += __shfl_xor_sync(0xffffffffu, suml, 1);
        suml += __shfl_xor_sync(0xffffffffu, suml, 2);
        sumh += __shfl_xor_sync(0xffffffffu, sumh, 1);
        sumh += __shfl_xor_sync(0xffffffffu, sumh, 2);
        ll = ll * cl + suml; lh = lh * ch + sumh;
        ml = nml; mh = nmh;
#pragma unroll
        for (int nf = 0; nf < 8; nf++) {
            o[nf][0] *= cl; o[nf][1] *= cl;
            o[nf][2] *= ch; o[nf][3] *= ch;
        }

        // write P (tf32) to per-warp rows of Ps
#pragma unroll
        for (int nf = 0; nf < 8; nf++) {
            Ps[(rb + g) * PSTR + nf * 8 + 2 * t]     = f2t(s[nf][0]);
            Ps[(rb + g) * PSTR + nf * 8 + 2 * t + 1] = f2t(s[nf][1]);
            Ps[(rb + g + 8) * PSTR + nf * 8 + 2 * t]     = f2t(s[nf][2]);
            Ps[(rb + g + 8) * PSTR + nf * 8 + 2 * t + 1] = f2t(s[nf][3]);
        }
        __syncwarp();

        // O += P V
        unsigned pa[8][4];
#pragma unroll
        for (int j8 = 0; j8 < 8; j8++) {
            pa[j8][0] = Ps[(rb + g) * PSTR + j8 * 8 + t];
            pa[j8][1] = Ps[(rb + g + 8) * PSTR + j8 * 8 + t];
            pa[j8][2] = Ps[(rb + g) * PSTR + j8 * 8 + t + 4];
            pa[j8][3] = Ps[(rb + g + 8) * PSTR + j8 * 8 + t + 4];
        }
#pragma unroll
        for (int nf = 0; nf < 8; nf++) {
#pragma unroll
            for (int j8 = 0; j8 < 8; j8++) {
                unsigned vb[2];
                vb[0] = Vs[(j8 * 8 + t) * VSTR + nf * 8 + g];
                vb[1] = Vs[(j8 * 8 + t + 4) * VSTR + nf * 8 + g];
                mma8(o[nf], pa[j8], vb);
            }
        }
    }

    // normalize + store merged heads
    const int b_ = bh >> 4, h = bh & 15;
    float rl = 1.f / ll, rh = 1.f / lh;
    int rlo = qi * 64 + rb + g, rhi = rlo + 8;
#pragma unroll
    for (int nf = 0; nf < 8; nf++) {
        int d = nf * 8 + 2 * t;
        *(float2*)(g_attn + (size_t)(b_ * SS + rlo) * DD + h * HD + d) =
            make_float2(o[nf][0] * rl, o[nf][1] * rl);
        *(float2*)(g_attn + (size_t)(b_ * SS + rhi) * DD + h * HD + d) =
            make_float2(o[nf][2] * rh, o[nf][3] * rh);
    }
}

// ---------------------------------------------------------------------------
extern "C" void kernel_launch(void* const* d_in, const int* in_sizes, int n_in,
                              void* d_out, int out_size)
{
    const float* hs     = (const float*)d_in[0];
    const float* lora   = (const float*)d_in[1];
    const float* w_attn = (const float*)d_in[2];
    const float* b_attn = (const float*)d_in[3];
    const float* w_proj = (const float*)d_in[4];
    const float* b_proj = (const float*)d_in[5];
    float* out = (float*)d_out;

    cudaFuncSetAttribute(gemm_tf32<D3, true>,
                         cudaFuncAttributeMaxDynamicSharedMemorySize, GSMEM);
    cudaFuncSetAttribute(gemm_tf32<DD, false>,
                         cudaFuncAttributeMaxDynamicSharedMemorySize, GSMEM);
    cudaFuncSetAttribute(flash_tf32,
                         cudaFuncAttributeMaxDynamicSharedMemorySize, FSMEM);

    gemm_tf32<D3, true><<<dim3(D3 / 128, MTOT / 128), 256, GSMEM>>>(
        hs, w_attn, b_attn, lora, nullptr);
    flash_tf32<<<dim3(SS / 64, NB * NH), 128, FSMEM>>>();
    gemm_tf32<DD, false><<<dim3(DD / 128, MTOT / 128), 256, GSMEM>>>(
        nullptr, w_proj, b_proj, nullptr, out);
}